// round 16
// baseline (speedup 1.0000x reference)
#include <cuda_runtime.h>
#include <cuda_bf16.h>
#include <cstdint>

// Problem dims (fixed by dataset)
#define PN0 10000
#define PN1 100000
#define PN2 1000000
#define PE0 100000
#define PE1 1000000
#define PDIN 128
#define PDH  256
#define PDOUT 47

// ---------------- scratch (device globals; no allocation allowed) -------------
__device__ float g_sum1[PN1 * PDIN];     // a1 in-place after finalize
__device__ float g_deg1[PN1];
__device__ float g_n1[PN1 * PDH];
__device__ float g_sum0[PN0 * PDIN];     // a0 in-place
__device__ float g_deg0[PN0];
__device__ float g_n0[PN0 * PDH];
__device__ float g_sumA[PN0 * PDH];      // final a in-place

__device__ unsigned g_mask_h2 [PN2 * PDIN / 32];
__device__ unsigned g_mask_h1s[PN1 * PDIN / 32];
__device__ unsigned g_mask_n1 [PN1 * PDH  / 32];
__device__ unsigned g_flag2  [PN2];      // h2 row claim/ready flags (0/1/2)
__device__ unsigned g_flag1  [PN1];      // h1s/mn1 row-claim flags

// ---------------- threefry2x32 (JAX-exact, 20 rounds) ------------------------
__host__ __device__ __forceinline__ void tf2x32(unsigned k0, unsigned k1,
                                                unsigned x0, unsigned x1,
                                                unsigned &o0, unsigned &o1) {
  unsigned ks2 = k0 ^ k1 ^ 0x1BD11BDAu;
#ifdef __CUDA_ARCH__
#define TF_ROT(x, r) __funnelshift_l((x), (x), (r))
#else
#define TF_ROT(x, r) (((x) << (r)) | ((x) >> (32 - (r))))
#endif
#define TF_RND(r) { x0 += x1; x1 = TF_ROT(x1, r); x1 ^= x0; }
  x0 += k0; x1 += k1;
  TF_RND(13) TF_RND(15) TF_RND(26) TF_RND(6)
  x0 += k1;  x1 += ks2 + 1u;
  TF_RND(17) TF_RND(29) TF_RND(16) TF_RND(24)
  x0 += ks2; x1 += k0 + 2u;
  TF_RND(13) TF_RND(15) TF_RND(26) TF_RND(6)
  x0 += k0;  x1 += k1 + 3u;
  TF_RND(17) TF_RND(29) TF_RND(16) TF_RND(24)
  x0 += k1;  x1 += ks2 + 4u;
  TF_RND(13) TF_RND(15) TF_RND(26) TF_RND(6)
  x0 += ks2; x1 += k0 + 5u;
#undef TF_RND
#undef TF_ROT
  o0 = x0; o1 = x1;
}

__device__ __forceinline__ unsigned ld_acq(const unsigned *p) {
  unsigned v;
  asm volatile("ld.global.acquire.gpu.b32 %0, [%1];" : "=r"(v) : "l"(p) : "memory");
  return v;
}

// ---------------- fused h2 maskgen + edge gather (E1 hop, C=128) --------------
__global__ __launch_bounds__(256) void fused_h2_gather_kernel(
    unsigned k0, unsigned k1, const float *__restrict__ feat,
    const int *__restrict__ rowmap, const int *__restrict__ src,
    const int *__restrict__ dst, unsigned *__restrict__ flag,
    unsigned *__restrict__ mask, float *__restrict__ sum,
    float *__restrict__ deg, int E) {
  int e = (blockIdx.x * blockDim.x + threadIdx.x) >> 5;
  if (e >= E) return;
  int lane = threadIdx.x & 31;
  int r = src[e];
  int d = dst[e];
  unsigned state = 0;
  if (lane == 0) {
    atomicAdd(&deg[d], 1.0f);
    state = atomicCAS(&flag[r], 0u, 1u);
  }
  state = __shfl_sync(0xffffffffu, state, 0);

  unsigned mw;
  if (state == 0) {
    unsigned base = (unsigned)r * 128u + (unsigned)lane;
    unsigned bw[4];
#pragma unroll
    for (int k = 0; k < 4; k++) {
      unsigned o0, o1;
      tf2x32(k0, k1, 0u, base + 32u * k, o0, o1);
      bw[k] = __ballot_sync(0xffffffffu, !((o0 ^ o1) >> 31));
    }
    if (lane == 0) {
      mask[r * 4 + 0] = bw[0];
      mask[r * 4 + 1] = bw[1];
      mask[r * 4 + 2] = bw[2];
      mask[r * 4 + 3] = bw[3];
      __threadfence();
      atomicExch(&flag[r], 2u);
    }
    mw = bw[lane >> 3];
  } else {
    if (state == 1) {
      if (lane == 0) {
        while (ld_acq(&flag[r]) != 2u) { __nanosleep(64); }
      }
      __syncwarp();
    }
    __threadfence();
    mw = mask[r * 4 + (lane >> 3)];
  }

  size_t g = (size_t)rowmap[r];
  int c0 = lane * 4;
  float4 v = *reinterpret_cast<const float4 *>(feat + g * 128 + c0);
  int sh = (lane & 7) * 4;
  float a0 = ((mw >> (sh + 0)) & 1u) ? 2.0f * v.x : 0.0f;
  float a1 = ((mw >> (sh + 1)) & 1u) ? 2.0f * v.y : 0.0f;
  float a2 = ((mw >> (sh + 2)) & 1u) ? 2.0f * v.z : 0.0f;
  float a3 = ((mw >> (sh + 3)) & 1u) ? 2.0f * v.w : 0.0f;
  float *s = sum + (size_t)d * 128 + c0;
  asm volatile("red.global.add.v4.f32 [%0], {%1,%2,%3,%4};"
               :: "l"(s), "f"(a0), "f"(a1), "f"(a2), "f"(a3) : "memory");
}

// ---------------- combined claim maskgen for h1s (4 words) + mn1 (8 words) ----
__global__ __launch_bounds__(256) void maskgen_pair_kernel(
    unsigned a0, unsigned a1, unsigned b0, unsigned b1,
    const int *__restrict__ src, int E, unsigned *__restrict__ flag,
    unsigned *__restrict__ maskA, unsigned *__restrict__ maskB) {
  int e = (blockIdx.x * blockDim.x + threadIdx.x) >> 5;
  if (e >= E) return;
  int lane = threadIdx.x & 31;
  int r = src[e];
  unsigned claimed = 0;
  if (lane == 0) claimed = (atomicExch(&flag[r], 1u) == 0u);
  claimed = __shfl_sync(0xffffffffu, claimed, 0);
  if (!claimed) return;
  unsigned baseA = (unsigned)r * 128u + (unsigned)lane;
  unsigned baseB = (unsigned)r * 256u + (unsigned)lane;
  unsigned keepA[4], keepB[8];
#pragma unroll
  for (int k = 0; k < 4; k++) {
    unsigned o0, o1;
    tf2x32(a0, a1, 0u, baseA + 32u * k, o0, o1);
    keepA[k] = !((o0 ^ o1) >> 31);
  }
#pragma unroll
  for (int k = 0; k < 8; k++) {
    unsigned o0, o1;
    tf2x32(b0, b1, 0u, baseB + 32u * k, o0, o1);
    keepB[k] = !((o0 ^ o1) >> 31);
  }
#pragma unroll
  for (int k = 0; k < 4; k++) {
    unsigned b = __ballot_sync(0xffffffffu, keepA[k]);
    if (lane == 0) maskA[r * 4 + k] = b;
  }
#pragma unroll
  for (int k = 0; k < 8; k++) {
    unsigned b = __ballot_sync(0xffffffffu, keepB[k]);
    if (lane == 0) maskB[r * 8 + k] = b;
  }
}

// ---------------- edge gather + segment-sum (one warp per edge) --------------
__global__ __launch_bounds__(256) void edge_gather_kernel(
    const float *__restrict__ feat, const int *__restrict__ rowmap,
    const int *__restrict__ src, const int *__restrict__ dst,
    const unsigned *__restrict__ mask, float *__restrict__ sum,
    float *__restrict__ deg, int E, int C) {
  int e = (blockIdx.x * blockDim.x + threadIdx.x) >> 5;
  if (e >= E) return;
  int lane = threadIdx.x & 31;
  int r = src[e];
  int d = dst[e];
  size_t g = rowmap ? (size_t)rowmap[r] : (size_t)r;
  if (deg && lane == 0) atomicAdd(&deg[d], 1.0f);
  const float4 *fr = reinterpret_cast<const float4 *>(feat + g * (size_t)C);
  for (int c0 = lane * 4; c0 < C; c0 += 128) {
    float4 v = fr[c0 >> 2];
    unsigned mw = mask[r * (C >> 5) + (c0 >> 5)];
    int sh = c0 & 31;
    float a0 = ((mw >> (sh + 0)) & 1u) ? 2.0f * v.x : 0.0f;
    float a1 = ((mw >> (sh + 1)) & 1u) ? 2.0f * v.y : 0.0f;
    float a2 = ((mw >> (sh + 2)) & 1u) ? 2.0f * v.z : 0.0f;
    float a3 = ((mw >> (sh + 3)) & 1u) ? 2.0f * v.w : 0.0f;
    float *s = sum + (size_t)d * C + c0;
    asm volatile("red.global.add.v4.f32 [%0], {%1,%2,%3,%4};"
                 :: "l"(s), "f"(a0), "f"(a1), "f"(a2), "f"(a3) : "memory");
  }
}

// ---------------- finalize with FUSED self-dropout RNG -----------------------
__global__ __launch_bounds__(256) void finalize_rng_kernel(
    float *__restrict__ sum, const float *__restrict__ deg,
    const float *__restrict__ selfFeat, const int *__restrict__ rowmap,
    unsigned k0, unsigned k1, int Nr, int C) {
  int idx = blockIdx.x * blockDim.x + threadIdx.x;
  int perRow = C >> 2;
  if (idx >= Nr * perRow) return;
  int i = idx / perRow;
  int c0 = (idx - i * perRow) << 2;
  float d = deg[i];
  float inv = d > 0.f ? 1.0f / d : 0.f;
  size_t g = rowmap ? (size_t)rowmap[i] : (size_t)i;
  float4 hv = *reinterpret_cast<const float4 *>(selfFeat + g * (size_t)C + c0);
  unsigned jb = (unsigned)i * (unsigned)C + (unsigned)c0;
  unsigned keep[4];
#pragma unroll
  for (int t = 0; t < 4; t++) {
    unsigned o0, o1;
    tf2x32(k0, k1, 0u, jb + t, o0, o1);
    keep[t] = !((o0 ^ o1) >> 31);
  }
  float4 sv = *reinterpret_cast<const float4 *>(sum + (size_t)i * C + c0);
  float r0 = sv.x * inv + (keep[0] ? 2.f * hv.x : 0.f);
  float r1 = sv.y * inv + (keep[1] ? 2.f * hv.y : 0.f);
  float r2 = sv.z * inv + (keep[2] ? 2.f * hv.z : 0.f);
  float r3 = sv.w * inv + (keep[3] ? 2.f * hv.w : 0.f);
  float4 o = make_float4(fmaxf(r0, 0.f), fmaxf(r1, 0.f),
                         fmaxf(r2, 0.f), fmaxf(r3, 0.f));
  *reinterpret_cast<float4 *>(sum + (size_t)i * C + c0) = o;
}

// ---------------- 3xTF32 tensor-core GEMM: C[M,256] = A[M,128]@B[128,256]+bias
// Block tile 128x64, 8 warps (4m x 2n), warp tile 32x32 = 2x4 m16n8k8 tiles.
// smem holds fragment-ordered A/B so frag loads are single LDS.128 / LDS.64.
// 3xTF32: x = hi + lo (both tf32); D += hi*hi + hi*lo + lo*hi  (err ~2^-22).
__device__ __forceinline__ unsigned f2tf32(float x) {
  unsigned r;
  asm("cvt.rna.tf32.f32 %0, %1;" : "=r"(r) : "f"(x));
  return r;
}
__device__ __forceinline__ void mma_tf32(float *c, const unsigned *a,
                                         const unsigned *b) {
  asm volatile(
      "mma.sync.aligned.m16n8k8.row.col.f32.tf32.tf32.f32 "
      "{%0,%1,%2,%3}, {%4,%5,%6,%7}, {%8,%9}, {%0,%1,%2,%3};"
      : "+f"(c[0]), "+f"(c[1]), "+f"(c[2]), "+f"(c[3])
      : "r"(a[0]), "r"(a[1]), "r"(a[2]), "r"(a[3]), "r"(b[0]), "r"(b[1]));
}

__global__ __launch_bounds__(256) void gemm_tf32_bias_k128_n256(
    const float *__restrict__ A, const float *__restrict__ B,
    const float *__restrict__ bias, float *__restrict__ C, int M) {
  // AsF[mt(8)][kt(4)][lane(32)][4]  = 16KB ; BsF[kt(4)][nt(8)][lane(32)][2] = 8KB
  __shared__ float AsF[8 * 4 * 32 * 4];
  __shared__ float BsF[4 * 8 * 32 * 2];
  int tid = threadIdx.x;
  int wid = tid >> 5;
  int lane = tid & 31;
  int row0 = blockIdx.y * 128;
  int col0 = blockIdx.x * 64;
  int wm = wid & 3;   // 0..3 -> 32-row slab
  int wn = wid >> 2;  // 0..1 -> 32-col slab

  float acc[2][4][4];
#pragma unroll
  for (int t = 0; t < 2; t++)
#pragma unroll
    for (int j = 0; j < 4; j++)
#pragma unroll
      for (int q = 0; q < 4; q++) acc[t][j][q] = 0.f;

  for (int kk = 0; kk < 128; kk += 32) {
    // ---- load A chunk [128 x 32] into fragment layout ----
#pragma unroll
    for (int i = 0; i < 4; i++) {
      int f = tid + i * 256;       // 0..1023
      int row = f >> 3;            // 0..127
      int c8 = f & 7;              // float4 index within 32 cols
      float4 v;
      if (row0 + row < M)
        v = *reinterpret_cast<const float4 *>(A + (size_t)(row0 + row) * 128 +
                                              kk + c8 * 4);
      else
        v = make_float4(0.f, 0.f, 0.f, 0.f);
      int kt = c8 >> 1;
      int c4 = c8 & 1;
      int rr = row & 7;
      int r8 = (row >> 3) & 1;
      int mt = row >> 4;
      int idx = r8 + 2 * c4;
      float vv[4] = {v.x, v.y, v.z, v.w};
#pragma unroll
      for (int cc = 0; cc < 4; cc++) {
        int ln = rr * 4 + cc;
        AsF[((mt * 4 + kt) * 32 + ln) * 4 + idx] = vv[cc];
      }
    }
    // ---- load B chunk [32 x 64] into fragment layout ----
#pragma unroll
    for (int i = 0; i < 2; i++) {
      int f = tid + i * 256;       // 0..511
      int krow = f >> 4;           // 0..31
      int c16 = f & 15;            // float4 index within 64 cols
      float4 v = *reinterpret_cast<const float4 *>(B + (size_t)(kk + krow) * 256 +
                                                   col0 + c16 * 4);
      int kt = krow >> 3;
      int klow = krow & 7;
      int idx = klow >> 2;
      int l3 = klow & 3;
      float vv[4] = {v.x, v.y, v.z, v.w};
#pragma unroll
      for (int cc = 0; cc < 4; cc++) {
        int ncol = c16 * 4 + cc;
        int nt = ncol >> 3;
        int nn = ncol & 7;
        int ln = nn * 4 + l3;
        BsF[((kt * 8 + nt) * 32 + ln) * 2 + idx] = vv[cc];
      }
    }
    __syncthreads();

    // ---- compute: 4 k8-steps ----
#pragma unroll
    for (int kt = 0; kt < 4; kt++) {
      unsigned ahi[2][4], alo[2][4];
#pragma unroll
      for (int t = 0; t < 2; t++) {
        int mt = wm * 2 + t;
        float4 a = *reinterpret_cast<const float4 *>(
            &AsF[((mt * 4 + kt) * 32 + lane) * 4]);
        float av[4] = {a.x, a.y, a.z, a.w};
#pragma unroll
        for (int e = 0; e < 4; e++) {
          unsigned h = f2tf32(av[e]);
          ahi[t][e] = h;
          alo[t][e] = f2tf32(av[e] - __uint_as_float(h));
        }
      }
      unsigned bhi[4][2], blo[4][2];
#pragma unroll
      for (int j = 0; j < 4; j++) {
        int nt = wn * 4 + j;
        float2 b = *reinterpret_cast<const float2 *>(
            &BsF[((kt * 8 + nt) * 32 + lane) * 2]);
        float bv[2] = {b.x, b.y};
#pragma unroll
        for (int e = 0; e < 2; e++) {
          unsigned h = f2tf32(bv[e]);
          bhi[j][e] = h;
          blo[j][e] = f2tf32(bv[e] - __uint_as_float(h));
        }
      }
#pragma unroll
      for (int t = 0; t < 2; t++)
#pragma unroll
        for (int j = 0; j < 4; j++) {
          mma_tf32(acc[t][j], ahi[t], bhi[j]);
          mma_tf32(acc[t][j], ahi[t], blo[j]);
          mma_tf32(acc[t][j], alo[t], bhi[j]);
        }
    }
    __syncthreads();
  }

  // ---- epilogue ----
  int r = lane >> 2;
  int cq = lane & 3;
#pragma unroll
  for (int t = 0; t < 2; t++) {
#pragma unroll
    for (int j = 0; j < 4; j++) {
      int col = col0 + wn * 32 + j * 8 + cq * 2;
      float b0 = bias[col], b1 = bias[col + 1];
      int gr0 = row0 + wm * 32 + t * 16 + r;
      int gr1 = gr0 + 8;
      if (gr0 < M) {
        float2 o = make_float2(acc[t][j][0] + b0, acc[t][j][1] + b1);
        *reinterpret_cast<float2 *>(C + (size_t)gr0 * 256 + col) = o;
      }
      if (gr1 < M) {
        float2 o = make_float2(acc[t][j][2] + b0, acc[t][j][3] + b1);
        *reinterpret_cast<float2 *>(C + (size_t)gr1 * 256 + col) = o;
      }
    }
  }
}

// ---------------- SGEMM 128x64 tile, 8x4 microtile, bias (small GEMM) --------
__global__ __launch_bounds__(256) void sgemm_bias_128x64(
    const float *__restrict__ A, const float *__restrict__ B,
    const float *__restrict__ bias, float *__restrict__ C,
    int M, int N, int K) {
  __shared__ float As[16][132];
  __shared__ float Bs[16][68];
  int tid = threadIdx.x;
  int row0 = blockIdx.y * 128;
  int col0 = blockIdx.x * 64;
  int tr = tid >> 4;
  int tc = tid & 15;
  float acc[8][4];
#pragma unroll
  for (int i = 0; i < 8; i++)
#pragma unroll
    for (int j = 0; j < 4; j++) acc[i][j] = 0.f;

  int ar = tid >> 1;
  int ak = (tid & 1) * 8;
  int bk = tid >> 4;
  int bc = (tid & 15) * 4;

  for (int kk = 0; kk < K; kk += 16) {
    float4 a0, a1;
    if (row0 + ar < M) {
      const float *ap = A + (size_t)(row0 + ar) * K + kk + ak;
      a0 = *reinterpret_cast<const float4 *>(ap);
      a1 = *reinterpret_cast<const float4 *>(ap + 4);
    } else {
      a0 = make_float4(0.f, 0.f, 0.f, 0.f);
      a1 = a0;
    }
    As[ak + 0][ar] = a0.x; As[ak + 1][ar] = a0.y;
    As[ak + 2][ar] = a0.z; As[ak + 3][ar] = a0.w;
    As[ak + 4][ar] = a1.x; As[ak + 5][ar] = a1.y;
    As[ak + 6][ar] = a1.z; As[ak + 7][ar] = a1.w;
#pragma unroll
    for (int j = 0; j < 4; j++) {
      int c = col0 + bc + j;
      Bs[bk][bc + j] = (c < N) ? B[(size_t)(kk + bk) * N + c] : 0.f;
    }
    __syncthreads();
#pragma unroll
    for (int k = 0; k < 16; k++) {
      float a8[8], b4[4];
      *reinterpret_cast<float4 *>(a8)     = *reinterpret_cast<const float4 *>(&As[k][tr * 8]);
      *reinterpret_cast<float4 *>(a8 + 4) = *reinterpret_cast<const float4 *>(&As[k][tr * 8 + 4]);
      *reinterpret_cast<float4 *>(b4)     = *reinterpret_cast<const float4 *>(&Bs[k][tc * 4]);
#pragma unroll
      for (int i = 0; i < 8; i++)
#pragma unroll
        for (int j = 0; j < 4; j++) acc[i][j] += a8[i] * b4[j];
    }
    __syncthreads();
  }
#pragma unroll
  for (int i = 0; i < 8; i++) {
    int r = row0 + tr * 8 + i;
    if (r >= M) continue;
#pragma unroll
    for (int j = 0; j < 4; j++) {
      int c = col0 + tc * 4 + j;
      if (c < N) C[(size_t)r * N + c] = acc[i][j] + bias[c];
    }
  }
}

// ---------------- host orchestration -----------------------------------------
extern "C" void kernel_launch(void *const *d_in, const int *in_sizes, int n_in,
                              void *d_out, int out_size) {
  const float *features = (const float *)d_in[0];
  const int *s0 = (const int *)d_in[1];
  const int *s1 = (const int *)d_in[2];
  const int *s2 = (const int *)d_in[3];
  const int *src0 = (const int *)d_in[4];
  const int *dst0 = (const int *)d_in[5];
  const int *src1 = (const int *)d_in[6];
  const int *dst1 = (const int *)d_in[7];
  const float *W1 = (const float *)d_in[8];
  const float *b1 = (const float *)d_in[9];
  const float *W2 = (const float *)d_in[10];
  const float *b2 = (const float *)d_in[11];
  float *out = (float *)d_out;

  const int n0 = in_sizes[1];
  const int n1 = in_sizes[2];
  const int n2 = in_sizes[3];
  const int e0 = in_sizes[4];
  const int e1 = in_sizes[6];
  const int dh = in_sizes[9];          // 256
  const int dout = in_sizes[11];       // 47
  const int din = in_sizes[8] / dh;    // 128

  // ---- JAX key chain, threefry_partitionable=True semantics ----
  unsigned dk[3][2];
  tf2x32(0u, 42u, 0u, 0u, dk[0][0], dk[0][1]);
  tf2x32(0u, 42u, 0u, 1u, dk[1][0], dk[1][1]);
  tf2x32(0u, 42u, 0u, 2u, dk[2][0], dk[2][1]);
  unsigned kSrc[3][2], kSelf[3][2];
  for (int i = 0; i < 3; i++) {
    tf2x32(dk[i][0], dk[i][1], 0u, 0u, kSrc[i][0], kSrc[i][1]);
    tf2x32(dk[i][0], dk[i][1], 0u, 1u, kSelf[i][0], kSelf[i][1]);
  }

  // ---- scratch addresses ----
  void *p_sum1, *p_deg1, *p_n1, *p_sum0, *p_deg0, *p_n0, *p_sumA;
  void *p_flag2, *p_flag1, *p_mh2, *p_mh1s, *p_mn1;
  cudaGetSymbolAddress(&p_sum1, g_sum1);
  cudaGetSymbolAddress(&p_deg1, g_deg1);
  cudaGetSymbolAddress(&p_n1, g_n1);
  cudaGetSymbolAddress(&p_sum0, g_sum0);
  cudaGetSymbolAddress(&p_deg0, g_deg0);
  cudaGetSymbolAddress(&p_n0, g_n0);
  cudaGetSymbolAddress(&p_sumA, g_sumA);
  cudaGetSymbolAddress(&p_flag2, g_flag2);
  cudaGetSymbolAddress(&p_flag1, g_flag1);
  cudaGetSymbolAddress(&p_mh2, g_mask_h2);
  cudaGetSymbolAddress(&p_mh1s, g_mask_h1s);
  cudaGetSymbolAddress(&p_mn1, g_mask_n1);

  // ---- streams / events ----
  static cudaStream_t sB = nullptr, sC = nullptr;
  static cudaEvent_t evFork = nullptr, evZ0 = nullptr, evFused = nullptr,
                     evPair = nullptr, evC = nullptr;
  if (!sB) {
    cudaStreamCreateWithFlags(&sB, cudaStreamNonBlocking);
    cudaStreamCreateWithFlags(&sC, cudaStreamNonBlocking);
    cudaEventCreateWithFlags(&evFork, cudaEventDisableTiming);
    cudaEventCreateWithFlags(&evZ0, cudaEventDisableTiming);
    cudaEventCreateWithFlags(&evFused, cudaEventDisableTiming);
    cudaEventCreateWithFlags(&evPair, cudaEventDisableTiming);
    cudaEventCreateWithFlags(&evC, cudaEventDisableTiming);
  }
  cudaStream_t S = 0;  // legacy default = capture/origin stream

  // ---- S: zero what the fused kernel needs, then run it ----
  cudaMemsetAsync(p_flag2, 0, (size_t)n2 * sizeof(unsigned), S);
  cudaMemsetAsync(p_flag1, 0, (size_t)n1 * sizeof(unsigned), S);
  cudaMemsetAsync(p_sum1, 0, (size_t)n1 * din * sizeof(float), S);
  cudaMemsetAsync(p_deg1, 0, (size_t)n1 * sizeof(float), S);
  cudaEventRecord(evFork, S);
  {
    int blocks = (e1 * 32 + 255) / 256;
    fused_h2_gather_kernel<<<blocks, 256, 0, S>>>(
        kSrc[1][0], kSrc[1][1], features, s2, src1, dst1,
        (unsigned *)p_flag2, (unsigned *)p_mh2, (float *)p_sum1,
        (float *)p_deg1, e1);
  }
  cudaEventRecord(evFused, S);

  // ---- S: finalize1 (fused h1f RNG) + gemm1 (tf32 tensor) ----
  {
    int fb = (n1 * (din / 4) + 255) / 256;
    finalize_rng_kernel<<<fb, 256, 0, S>>>((float *)p_sum1, (float *)p_deg1,
                                           features, s1, kSelf[1][0],
                                           kSelf[1][1], n1, din);
    dim3 grid(4, (n1 + 127) / 128);
    gemm_tf32_bias_k128_n256<<<grid, 256, 0, S>>>((float *)p_sum1, W1, b1,
                                                  (float *)p_n1, n1);
  }

  // ---- sC: remaining accumulator memsets (overlap fused kernel) ----
  cudaStreamWaitEvent(sC, evFork, 0);
  cudaMemsetAsync(p_sum0, 0, (size_t)n0 * din * sizeof(float), sC);
  cudaMemsetAsync(p_deg0, 0, (size_t)n0 * sizeof(float), sC);
  cudaMemsetAsync(p_sumA, 0, (size_t)n0 * dh * sizeof(float), sC);
  cudaEventRecord(evZ0, sC);

  // ---- sB: h1s+mn1 claim maskgen, gated after fused (hides under gemm1) ----
  cudaStreamWaitEvent(sB, evFused, 0);
  {
    int blocks = (e0 * 32 + 255) / 256;
    maskgen_pair_kernel<<<blocks, 256, 0, sB>>>(
        kSrc[0][0], kSrc[0][1], kSrc[2][0], kSrc[2][1], src0, e0,
        (unsigned *)p_flag1, (unsigned *)p_mh1s, (unsigned *)p_mn1);
  }
  cudaEventRecord(evPair, sB);

  // ---- sC: a0 branch (hides under gemm1 on S) ----
  cudaStreamWaitEvent(sC, evPair, 0);
  {
    int blocks = (e0 * 32 + 255) / 256;
    edge_gather_kernel<<<blocks, 256, 0, sC>>>(features, s1, src0, dst0,
                                               (unsigned *)p_mh1s,
                                               (float *)p_sum0,
                                               (float *)p_deg0, e0, din);
    int fb = (n0 * (din / 4) + 255) / 256;
    finalize_rng_kernel<<<fb, 256, 0, sC>>>((float *)p_sum0, (float *)p_deg0,
                                            features, s0, kSelf[0][0],
                                            kSelf[0][1], n0, din);
    dim3 grid(4, (n0 + 127) / 128);
    gemm_tf32_bias_k128_n256<<<grid, 256, 0, sC>>>((float *)p_sum0, W1, b1,
                                                   (float *)p_n0, n0);
  }
  cudaEventRecord(evC, sC);

  // ---- S: final layer ----
  cudaStreamWaitEvent(S, evPair, 0);  // mn1 mask
  cudaStreamWaitEvent(S, evZ0, 0);    // sumA zeroed
  {
    int blocks = (e0 * 32 + 255) / 256;
    edge_gather_kernel<<<blocks, 256, 0, S>>>((float *)p_n1, nullptr, src0,
                                              dst0, (unsigned *)p_mn1,
                                              (float *)p_sumA, nullptr, e0, dh);
  }
  cudaStreamWaitEvent(S, evC, 0);  // n0 + deg0 ready
  {
    int fb = (n0 * (dh / 4) + 255) / 256;
    finalize_rng_kernel<<<fb, 256, 0, S>>>((float *)p_sumA, (float *)p_deg0,
                                           (float *)p_n0, nullptr, kSelf[2][0],
                                           kSelf[2][1], n0, dh);
    dim3 grid((dout + 63) / 64, (n0 + 127) / 128);
    sgemm_bias_128x64<<<grid, 256, 0, S>>>((float *)p_sumA, W2, b2, out, n0,
                                           dout, dh);
  }
}

// round 17
// speedup vs baseline: 1.0261x; 1.0261x over previous
#include <cuda_runtime.h>
#include <cuda_bf16.h>
#include <cstdint>

// Problem dims (fixed by dataset)
#define PN0 10000
#define PN1 100000
#define PN2 1000000
#define PE0 100000
#define PE1 1000000
#define PDIN 128
#define PDH  256
#define PDOUT 47

// ---------------- scratch (device globals; no allocation allowed) -------------
__device__ float g_sum1[PN1 * PDIN];     // a1 in-place after finalize
__device__ float g_deg1[PN1];
__device__ float g_n1[PN1 * PDH];
__device__ float g_sum0[PN0 * PDIN];     // a0 in-place
__device__ float g_deg0[PN0];
__device__ float g_n0[PN0 * PDH];
__device__ float g_sumA[PN0 * PDH];      // final a in-place

__device__ unsigned g_mask_h2 [PN2 * PDIN / 32];
__device__ unsigned g_mask_h1s[PN1 * PDIN / 32];
__device__ unsigned g_mask_n1 [PN1 * PDH  / 32];
__device__ unsigned g_flag2  [PN2];      // h2 row claim/ready flags (0/1/2)
__device__ unsigned g_flag1  [PN1];      // h1s/mn1 row-claim flags

// ---------------- threefry2x32 (JAX-exact, 20 rounds) ------------------------
__host__ __device__ __forceinline__ void tf2x32(unsigned k0, unsigned k1,
                                                unsigned x0, unsigned x1,
                                                unsigned &o0, unsigned &o1) {
  unsigned ks2 = k0 ^ k1 ^ 0x1BD11BDAu;
#ifdef __CUDA_ARCH__
#define TF_ROT(x, r) __funnelshift_l((x), (x), (r))
#else
#define TF_ROT(x, r) (((x) << (r)) | ((x) >> (32 - (r))))
#endif
#define TF_RND(r) { x0 += x1; x1 = TF_ROT(x1, r); x1 ^= x0; }
  x0 += k0; x1 += k1;
  TF_RND(13) TF_RND(15) TF_RND(26) TF_RND(6)
  x0 += k1;  x1 += ks2 + 1u;
  TF_RND(17) TF_RND(29) TF_RND(16) TF_RND(24)
  x0 += ks2; x1 += k0 + 2u;
  TF_RND(13) TF_RND(15) TF_RND(26) TF_RND(6)
  x0 += k0;  x1 += k1 + 3u;
  TF_RND(17) TF_RND(29) TF_RND(16) TF_RND(24)
  x0 += k1;  x1 += ks2 + 4u;
  TF_RND(13) TF_RND(15) TF_RND(26) TF_RND(6)
  x0 += ks2; x1 += k0 + 5u;
#undef TF_RND
#undef TF_ROT
  o0 = x0; o1 = x1;
}

__device__ __forceinline__ unsigned ld_acq(const unsigned *p) {
  unsigned v;
  asm volatile("ld.global.acquire.gpu.b32 %0, [%1];" : "=r"(v) : "l"(p) : "memory");
  return v;
}
__device__ __forceinline__ void st_rel(unsigned *p, unsigned v) {
  asm volatile("st.global.release.gpu.b32 [%0], %1;" :: "l"(p), "r"(v) : "memory");
}

// ---------------- fused h2 maskgen + edge gather (E1 hop, C=128) --------------
// One warp per edge. First warp to CAS a src row computes its 128 mask bits
// (threefry + ballot), publishes with a release-store on the flag (orders the
// mask stores); duplicate warps acquire-spin on the flag then read the mask.
// No MEMBARs. The feature row load is hoisted so its DRAM latency overlaps the
// threefry compute / spin.
__global__ __launch_bounds__(256) void fused_h2_gather_kernel(
    unsigned k0, unsigned k1, const float *__restrict__ feat,
    const int *__restrict__ rowmap, const int *__restrict__ src,
    const int *__restrict__ dst, unsigned *__restrict__ flag,
    unsigned *__restrict__ mask, float *__restrict__ sum,
    float *__restrict__ deg, int E) {
  int e = (blockIdx.x * blockDim.x + threadIdx.x) >> 5;
  if (e >= E) return;
  int lane = threadIdx.x & 31;
  int r = src[e];
  int d = dst[e];

  // hoisted feature load: overlaps with claim/threefry/spin below
  size_t g = (size_t)rowmap[r];
  int c0 = lane * 4;
  float4 v = *reinterpret_cast<const float4 *>(feat + g * 128 + c0);

  unsigned state = 0;
  if (lane == 0) {
    atomicAdd(&deg[d], 1.0f);
    state = atomicCAS(&flag[r], 0u, 1u);
  }
  state = __shfl_sync(0xffffffffu, state, 0);

  unsigned mw;
  if (state == 0) {
    unsigned base = (unsigned)r * 128u + (unsigned)lane;
    unsigned bw[4];
#pragma unroll
    for (int k = 0; k < 4; k++) {
      unsigned o0, o1;
      tf2x32(k0, k1, 0u, base + 32u * k, o0, o1);
      bw[k] = __ballot_sync(0xffffffffu, !((o0 ^ o1) >> 31));
    }
    if (lane == 0) {
      mask[r * 4 + 0] = bw[0];
      mask[r * 4 + 1] = bw[1];
      mask[r * 4 + 2] = bw[2];
      mask[r * 4 + 3] = bw[3];
      st_rel(&flag[r], 2u);   // release: orders the 4 mask stores before flag=2
    }
    mw = bw[lane >> 3];
  } else {
    // acquire-spin (state==2 warps exit on first poll); __syncwarp provides
    // intra-warp memory ordering so all lanes' mask loads see the publish.
    if (lane == 0) {
      while (ld_acq(&flag[r]) != 2u) { __nanosleep(64); }
    }
    __syncwarp();
    mw = mask[r * 4 + (lane >> 3)];
  }

  int sh = (lane & 7) * 4;
  float a0 = ((mw >> (sh + 0)) & 1u) ? 2.0f * v.x : 0.0f;
  float a1 = ((mw >> (sh + 1)) & 1u) ? 2.0f * v.y : 0.0f;
  float a2 = ((mw >> (sh + 2)) & 1u) ? 2.0f * v.z : 0.0f;
  float a3 = ((mw >> (sh + 3)) & 1u) ? 2.0f * v.w : 0.0f;
  float *s = sum + (size_t)d * 128 + c0;
  asm volatile("red.global.add.v4.f32 [%0], {%1,%2,%3,%4};"
               :: "l"(s), "f"(a0), "f"(a1), "f"(a2), "f"(a3) : "memory");
}

// ---------------- combined claim maskgen for h1s (4 words) + mn1 (8 words) ----
__global__ __launch_bounds__(256) void maskgen_pair_kernel(
    unsigned a0, unsigned a1, unsigned b0, unsigned b1,
    const int *__restrict__ src, int E, unsigned *__restrict__ flag,
    unsigned *__restrict__ maskA, unsigned *__restrict__ maskB) {
  int e = (blockIdx.x * blockDim.x + threadIdx.x) >> 5;
  if (e >= E) return;
  int lane = threadIdx.x & 31;
  int r = src[e];
  unsigned claimed = 0;
  if (lane == 0) claimed = (atomicExch(&flag[r], 1u) == 0u);
  claimed = __shfl_sync(0xffffffffu, claimed, 0);
  if (!claimed) return;
  unsigned baseA = (unsigned)r * 128u + (unsigned)lane;
  unsigned baseB = (unsigned)r * 256u + (unsigned)lane;
  unsigned keepA[4], keepB[8];
#pragma unroll
  for (int k = 0; k < 4; k++) {
    unsigned o0, o1;
    tf2x32(a0, a1, 0u, baseA + 32u * k, o0, o1);
    keepA[k] = !((o0 ^ o1) >> 31);
  }
#pragma unroll
  for (int k = 0; k < 8; k++) {
    unsigned o0, o1;
    tf2x32(b0, b1, 0u, baseB + 32u * k, o0, o1);
    keepB[k] = !((o0 ^ o1) >> 31);
  }
#pragma unroll
  for (int k = 0; k < 4; k++) {
    unsigned b = __ballot_sync(0xffffffffu, keepA[k]);
    if (lane == 0) maskA[r * 4 + k] = b;
  }
#pragma unroll
  for (int k = 0; k < 8; k++) {
    unsigned b = __ballot_sync(0xffffffffu, keepB[k]);
    if (lane == 0) maskB[r * 8 + k] = b;
  }
}

// ---------------- edge gather + segment-sum (one warp per edge) --------------
__global__ __launch_bounds__(256) void edge_gather_kernel(
    const float *__restrict__ feat, const int *__restrict__ rowmap,
    const int *__restrict__ src, const int *__restrict__ dst,
    const unsigned *__restrict__ mask, float *__restrict__ sum,
    float *__restrict__ deg, int E, int C) {
  int e = (blockIdx.x * blockDim.x + threadIdx.x) >> 5;
  if (e >= E) return;
  int lane = threadIdx.x & 31;
  int r = src[e];
  int d = dst[e];
  size_t g = rowmap ? (size_t)rowmap[r] : (size_t)r;
  if (deg && lane == 0) atomicAdd(&deg[d], 1.0f);
  const float4 *fr = reinterpret_cast<const float4 *>(feat + g * (size_t)C);
  for (int c0 = lane * 4; c0 < C; c0 += 128) {
    float4 v = fr[c0 >> 2];
    unsigned mw = mask[r * (C >> 5) + (c0 >> 5)];
    int sh = c0 & 31;
    float a0 = ((mw >> (sh + 0)) & 1u) ? 2.0f * v.x : 0.0f;
    float a1 = ((mw >> (sh + 1)) & 1u) ? 2.0f * v.y : 0.0f;
    float a2 = ((mw >> (sh + 2)) & 1u) ? 2.0f * v.z : 0.0f;
    float a3 = ((mw >> (sh + 3)) & 1u) ? 2.0f * v.w : 0.0f;
    float *s = sum + (size_t)d * C + c0;
    asm volatile("red.global.add.v4.f32 [%0], {%1,%2,%3,%4};"
                 :: "l"(s), "f"(a0), "f"(a1), "f"(a2), "f"(a3) : "memory");
  }
}

// ---------------- finalize with FUSED self-dropout RNG -----------------------
__global__ __launch_bounds__(256) void finalize_rng_kernel(
    float *__restrict__ sum, const float *__restrict__ deg,
    const float *__restrict__ selfFeat, const int *__restrict__ rowmap,
    unsigned k0, unsigned k1, int Nr, int C) {
  int idx = blockIdx.x * blockDim.x + threadIdx.x;
  int perRow = C >> 2;
  if (idx >= Nr * perRow) return;
  int i = idx / perRow;
  int c0 = (idx - i * perRow) << 2;
  float d = deg[i];
  float inv = d > 0.f ? 1.0f / d : 0.f;
  size_t g = rowmap ? (size_t)rowmap[i] : (size_t)i;
  float4 hv = *reinterpret_cast<const float4 *>(selfFeat + g * (size_t)C + c0);
  unsigned jb = (unsigned)i * (unsigned)C + (unsigned)c0;
  unsigned keep[4];
#pragma unroll
  for (int t = 0; t < 4; t++) {
    unsigned o0, o1;
    tf2x32(k0, k1, 0u, jb + t, o0, o1);
    keep[t] = !((o0 ^ o1) >> 31);
  }
  float4 sv = *reinterpret_cast<const float4 *>(sum + (size_t)i * C + c0);
  float r0 = sv.x * inv + (keep[0] ? 2.f * hv.x : 0.f);
  float r1 = sv.y * inv + (keep[1] ? 2.f * hv.y : 0.f);
  float r2 = sv.z * inv + (keep[2] ? 2.f * hv.z : 0.f);
  float r3 = sv.w * inv + (keep[3] ? 2.f * hv.w : 0.f);
  float4 o = make_float4(fmaxf(r0, 0.f), fmaxf(r1, 0.f),
                         fmaxf(r2, 0.f), fmaxf(r3, 0.f));
  *reinterpret_cast<float4 *>(sum + (size_t)i * C + c0) = o;
}

// ---------------- 3xTF32 tensor-core GEMM: C[M,256] = A[M,128]@B[128,256]+bias
__device__ __forceinline__ unsigned f2tf32(float x) {
  unsigned r;
  asm("cvt.rna.tf32.f32 %0, %1;" : "=r"(r) : "f"(x));
  return r;
}
__device__ __forceinline__ void mma_tf32(float *c, const unsigned *a,
                                         const unsigned *b) {
  asm volatile(
      "mma.sync.aligned.m16n8k8.row.col.f32.tf32.tf32.f32 "
      "{%0,%1,%2,%3}, {%4,%5,%6,%7}, {%8,%9}, {%0,%1,%2,%3};"
      : "+f"(c[0]), "+f"(c[1]), "+f"(c[2]), "+f"(c[3])
      : "r"(a[0]), "r"(a[1]), "r"(a[2]), "r"(a[3]), "r"(b[0]), "r"(b[1]));
}

__global__ __launch_bounds__(256) void gemm_tf32_bias_k128_n256(
    const float *__restrict__ A, const float *__restrict__ B,
    const float *__restrict__ bias, float *__restrict__ C, int M) {
  __shared__ float AsF[8 * 4 * 32 * 4];
  __shared__ float BsF[4 * 8 * 32 * 2];
  int tid = threadIdx.x;
  int wid = tid >> 5;
  int lane = tid & 31;
  int row0 = blockIdx.y * 128;
  int col0 = blockIdx.x * 64;
  int wm = wid & 3;
  int wn = wid >> 2;

  float acc[2][4][4];
#pragma unroll
  for (int t = 0; t < 2; t++)
#pragma unroll
    for (int j = 0; j < 4; j++)
#pragma unroll
      for (int q = 0; q < 4; q++) acc[t][j][q] = 0.f;

  for (int kk = 0; kk < 128; kk += 32) {
#pragma unroll
    for (int i = 0; i < 4; i++) {
      int f = tid + i * 256;
      int row = f >> 3;
      int c8 = f & 7;
      float4 v;
      if (row0 + row < M)
        v = *reinterpret_cast<const float4 *>(A + (size_t)(row0 + row) * 128 +
                                              kk + c8 * 4);
      else
        v = make_float4(0.f, 0.f, 0.f, 0.f);
      int kt = c8 >> 1;
      int c4 = c8 & 1;
      int rr = row & 7;
      int r8 = (row >> 3) & 1;
      int mt = row >> 4;
      int idx = r8 + 2 * c4;
      float vv[4] = {v.x, v.y, v.z, v.w};
#pragma unroll
      for (int cc = 0; cc < 4; cc++) {
        int ln = rr * 4 + cc;
        AsF[((mt * 4 + kt) * 32 + ln) * 4 + idx] = vv[cc];
      }
    }
#pragma unroll
    for (int i = 0; i < 2; i++) {
      int f = tid + i * 256;
      int krow = f >> 4;
      int c16 = f & 15;
      float4 v = *reinterpret_cast<const float4 *>(B + (size_t)(kk + krow) * 256 +
                                                   col0 + c16 * 4);
      int kt = krow >> 3;
      int klow = krow & 7;
      int idx = klow >> 2;
      int l3 = klow & 3;
      float vv[4] = {v.x, v.y, v.z, v.w};
#pragma unroll
      for (int cc = 0; cc < 4; cc++) {
        int ncol = c16 * 4 + cc;
        int nt = ncol >> 3;
        int nn = ncol & 7;
        int ln = nn * 4 + l3;
        BsF[((kt * 8 + nt) * 32 + ln) * 2 + idx] = vv[cc];
      }
    }
    __syncthreads();

#pragma unroll
    for (int kt = 0; kt < 4; kt++) {
      unsigned ahi[2][4], alo[2][4];
#pragma unroll
      for (int t = 0; t < 2; t++) {
        int mt = wm * 2 + t;
        float4 a = *reinterpret_cast<const float4 *>(
            &AsF[((mt * 4 + kt) * 32 + lane) * 4]);
        float av[4] = {a.x, a.y, a.z, a.w};
#pragma unroll
        for (int e = 0; e < 4; e++) {
          unsigned h = f2tf32(av[e]);
          ahi[t][e] = h;
          alo[t][e] = f2tf32(av[e] - __uint_as_float(h));
        }
      }
      unsigned bhi[4][2], blo[4][2];
#pragma unroll
      for (int j = 0; j < 4; j++) {
        int nt = wn * 4 + j;
        float2 b = *reinterpret_cast<const float2 *>(
            &BsF[((kt * 8 + nt) * 32 + lane) * 2]);
        float bv[2] = {b.x, b.y};
#pragma unroll
        for (int e = 0; e < 2; e++) {
          unsigned h = f2tf32(bv[e]);
          bhi[j][e] = h;
          blo[j][e] = f2tf32(bv[e] - __uint_as_float(h));
        }
      }
#pragma unroll
      for (int t = 0; t < 2; t++)
#pragma unroll
        for (int j = 0; j < 4; j++) {
          mma_tf32(acc[t][j], ahi[t], bhi[j]);
          mma_tf32(acc[t][j], ahi[t], blo[j]);
          mma_tf32(acc[t][j], alo[t], bhi[j]);
        }
    }
    __syncthreads();
  }

  int r = lane >> 2;
  int cq = lane & 3;
#pragma unroll
  for (int t = 0; t < 2; t++) {
#pragma unroll
    for (int j = 0; j < 4; j++) {
      int col = col0 + wn * 32 + j * 8 + cq * 2;
      float b0 = bias[col], b1 = bias[col + 1];
      int gr0 = row0 + wm * 32 + t * 16 + r;
      int gr1 = gr0 + 8;
      if (gr0 < M) {
        float2 o = make_float2(acc[t][j][0] + b0, acc[t][j][1] + b1);
        *reinterpret_cast<float2 *>(C + (size_t)gr0 * 256 + col) = o;
      }
      if (gr1 < M) {
        float2 o = make_float2(acc[t][j][2] + b0, acc[t][j][3] + b1);
        *reinterpret_cast<float2 *>(C + (size_t)gr1 * 256 + col) = o;
      }
    }
  }
}

// ---------------- SGEMM 128x64 tile, 8x4 microtile, bias (small GEMM) --------
__global__ __launch_bounds__(256) void sgemm_bias_128x64(
    const float *__restrict__ A, const float *__restrict__ B,
    const float *__restrict__ bias, float *__restrict__ C,
    int M, int N, int K) {
  __shared__ float As[16][132];
  __shared__ float Bs[16][68];
  int tid = threadIdx.x;
  int row0 = blockIdx.y * 128;
  int col0 = blockIdx.x * 64;
  int tr = tid >> 4;
  int tc = tid & 15;
  float acc[8][4];
#pragma unroll
  for (int i = 0; i < 8; i++)
#pragma unroll
    for (int j = 0; j < 4; j++) acc[i][j] = 0.f;

  int ar = tid >> 1;
  int ak = (tid & 1) * 8;
  int bk = tid >> 4;
  int bc = (tid & 15) * 4;

  for (int kk = 0; kk < K; kk += 16) {
    float4 a0, a1;
    if (row0 + ar < M) {
      const float *ap = A + (size_t)(row0 + ar) * K + kk + ak;
      a0 = *reinterpret_cast<const float4 *>(ap);
      a1 = *reinterpret_cast<const float4 *>(ap + 4);
    } else {
      a0 = make_float4(0.f, 0.f, 0.f, 0.f);
      a1 = a0;
    }
    As[ak + 0][ar] = a0.x; As[ak + 1][ar] = a0.y;
    As[ak + 2][ar] = a0.z; As[ak + 3][ar] = a0.w;
    As[ak + 4][ar] = a1.x; As[ak + 5][ar] = a1.y;
    As[ak + 6][ar] = a1.z; As[ak + 7][ar] = a1.w;
#pragma unroll
    for (int j = 0; j < 4; j++) {
      int c = col0 + bc + j;
      Bs[bk][bc + j] = (c < N) ? B[(size_t)(kk + bk) * N + c] : 0.f;
    }
    __syncthreads();
#pragma unroll
    for (int k = 0; k < 16; k++) {
      float a8[8], b4[4];
      *reinterpret_cast<float4 *>(a8)     = *reinterpret_cast<const float4 *>(&As[k][tr * 8]);
      *reinterpret_cast<float4 *>(a8 + 4) = *reinterpret_cast<const float4 *>(&As[k][tr * 8 + 4]);
      *reinterpret_cast<float4 *>(b4)     = *reinterpret_cast<const float4 *>(&Bs[k][tc * 4]);
#pragma unroll
      for (int i = 0; i < 8; i++)
#pragma unroll
        for (int j = 0; j < 4; j++) acc[i][j] += a8[i] * b4[j];
    }
    __syncthreads();
  }
#pragma unroll
  for (int i = 0; i < 8; i++) {
    int r = row0 + tr * 8 + i;
    if (r >= M) continue;
#pragma unroll
    for (int j = 0; j < 4; j++) {
      int c = col0 + tc * 4 + j;
      if (c < N) C[(size_t)r * N + c] = acc[i][j] + bias[c];
    }
  }
}

// ---------------- host orchestration -----------------------------------------
extern "C" void kernel_launch(void *const *d_in, const int *in_sizes, int n_in,
                              void *d_out, int out_size) {
  const float *features = (const float *)d_in[0];
  const int *s0 = (const int *)d_in[1];
  const int *s1 = (const int *)d_in[2];
  const int *s2 = (const int *)d_in[3];
  const int *src0 = (const int *)d_in[4];
  const int *dst0 = (const int *)d_in[5];
  const int *src1 = (const int *)d_in[6];
  const int *dst1 = (const int *)d_in[7];
  const float *W1 = (const float *)d_in[8];
  const float *b1 = (const float *)d_in[9];
  const float *W2 = (const float *)d_in[10];
  const float *b2 = (const float *)d_in[11];
  float *out = (float *)d_out;

  const int n0 = in_sizes[1];
  const int n1 = in_sizes[2];
  const int n2 = in_sizes[3];
  const int e0 = in_sizes[4];
  const int e1 = in_sizes[6];
  const int dh = in_sizes[9];          // 256
  const int dout = in_sizes[11];       // 47
  const int din = in_sizes[8] / dh;    // 128

  // ---- JAX key chain, threefry_partitionable=True semantics ----
  unsigned dk[3][2];
  tf2x32(0u, 42u, 0u, 0u, dk[0][0], dk[0][1]);
  tf2x32(0u, 42u, 0u, 1u, dk[1][0], dk[1][1]);
  tf2x32(0u, 42u, 0u, 2u, dk[2][0], dk[2][1]);
  unsigned kSrc[3][2], kSelf[3][2];
  for (int i = 0; i < 3; i++) {
    tf2x32(dk[i][0], dk[i][1], 0u, 0u, kSrc[i][0], kSrc[i][1]);
    tf2x32(dk[i][0], dk[i][1], 0u, 1u, kSelf[i][0], kSelf[i][1]);
  }

  // ---- scratch addresses ----
  void *p_sum1, *p_deg1, *p_n1, *p_sum0, *p_deg0, *p_n0, *p_sumA;
  void *p_flag2, *p_flag1, *p_mh2, *p_mh1s, *p_mn1;
  cudaGetSymbolAddress(&p_sum1, g_sum1);
  cudaGetSymbolAddress(&p_deg1, g_deg1);
  cudaGetSymbolAddress(&p_n1, g_n1);
  cudaGetSymbolAddress(&p_sum0, g_sum0);
  cudaGetSymbolAddress(&p_deg0, g_deg0);
  cudaGetSymbolAddress(&p_n0, g_n0);
  cudaGetSymbolAddress(&p_sumA, g_sumA);
  cudaGetSymbolAddress(&p_flag2, g_flag2);
  cudaGetSymbolAddress(&p_flag1, g_flag1);
  cudaGetSymbolAddress(&p_mh2, g_mask_h2);
  cudaGetSymbolAddress(&p_mh1s, g_mask_h1s);
  cudaGetSymbolAddress(&p_mn1, g_mask_n1);

  // ---- streams / events ----
  static cudaStream_t sB = nullptr, sC = nullptr;
  static cudaEvent_t evFork = nullptr, evZ0 = nullptr, evFused = nullptr,
                     evPair = nullptr, evC = nullptr;
  if (!sB) {
    cudaStreamCreateWithFlags(&sB, cudaStreamNonBlocking);
    cudaStreamCreateWithFlags(&sC, cudaStreamNonBlocking);
    cudaEventCreateWithFlags(&evFork, cudaEventDisableTiming);
    cudaEventCreateWithFlags(&evZ0, cudaEventDisableTiming);
    cudaEventCreateWithFlags(&evFused, cudaEventDisableTiming);
    cudaEventCreateWithFlags(&evPair, cudaEventDisableTiming);
    cudaEventCreateWithFlags(&evC, cudaEventDisableTiming);
  }
  cudaStream_t S = 0;  // legacy default = capture/origin stream

  // ---- S: zero what the fused kernel needs, then run it ----
  cudaMemsetAsync(p_flag2, 0, (size_t)n2 * sizeof(unsigned), S);
  cudaMemsetAsync(p_flag1, 0, (size_t)n1 * sizeof(unsigned), S);
  cudaMemsetAsync(p_sum1, 0, (size_t)n1 * din * sizeof(float), S);
  cudaMemsetAsync(p_deg1, 0, (size_t)n1 * sizeof(float), S);
  cudaEventRecord(evFork, S);
  {
    int blocks = (e1 * 32 + 255) / 256;
    fused_h2_gather_kernel<<<blocks, 256, 0, S>>>(
        kSrc[1][0], kSrc[1][1], features, s2, src1, dst1,
        (unsigned *)p_flag2, (unsigned *)p_mh2, (float *)p_sum1,
        (float *)p_deg1, e1);
  }
  cudaEventRecord(evFused, S);

  // ---- sB: h1s+mn1 claim maskgen, CONCURRENT with fused (fills its
  //      memory-stall issue slots; ALU total conserved) ----
  cudaStreamWaitEvent(sB, evFork, 0);
  {
    int blocks = (e0 * 32 + 255) / 256;
    maskgen_pair_kernel<<<blocks, 256, 0, sB>>>(
        kSrc[0][0], kSrc[0][1], kSrc[2][0], kSrc[2][1], src0, e0,
        (unsigned *)p_flag1, (unsigned *)p_mh1s, (unsigned *)p_mn1);
  }
  cudaEventRecord(evPair, sB);

  // ---- sC: remaining accumulator memsets + a0 branch (all under fused) ----
  cudaStreamWaitEvent(sC, evFork, 0);
  cudaMemsetAsync(p_sum0, 0, (size_t)n0 * din * sizeof(float), sC);
  cudaMemsetAsync(p_deg0, 0, (size_t)n0 * sizeof(float), sC);
  cudaMemsetAsync(p_sumA, 0, (size_t)n0 * dh * sizeof(float), sC);
  cudaEventRecord(evZ0, sC);
  cudaStreamWaitEvent(sC, evPair, 0);
  {
    int blocks = (e0 * 32 + 255) / 256;
    edge_gather_kernel<<<blocks, 256, 0, sC>>>(features, s1, src0, dst0,
                                               (unsigned *)p_mh1s,
                                               (float *)p_sum0,
                                               (float *)p_deg0, e0, din);
    int fb = (n0 * (din / 4) + 255) / 256;
    finalize_rng_kernel<<<fb, 256, 0, sC>>>((float *)p_sum0, (float *)p_deg0,
                                            features, s0, kSelf[0][0],
                                            kSelf[0][1], n0, din);
    dim3 grid(4, (n0 + 127) / 128);
    gemm_tf32_bias_k128_n256<<<grid, 256, 0, sC>>>((float *)p_sum0, W1, b1,
                                                   (float *)p_n0, n0);
  }
  cudaEventRecord(evC, sC);

  // ---- S: finalize1 + gemm1 (tf32) ----
  {
    int fb = (n1 * (din / 4) + 255) / 256;
    finalize_rng_kernel<<<fb, 256, 0, S>>>((float *)p_sum1, (float *)p_deg1,
                                           features, s1, kSelf[1][0],
                                           kSelf[1][1], n1, din);
    dim3 grid(4, (n1 + 127) / 128);
    gemm_tf32_bias_k128_n256<<<grid, 256, 0, S>>>((float *)p_sum1, W1, b1,
                                                  (float *)p_n1, n1);
  }

  // ---- S: final layer ----
  cudaStreamWaitEvent(S, evPair, 0);  // mn1 mask
  cudaStreamWaitEvent(S, evZ0, 0);    // sumA zeroed
  {
    int blocks = (e0 * 32 + 255) / 256;
    edge_gather_kernel<<<blocks, 256, 0, S>>>((float *)p_n1, nullptr, src0,
                                              dst0, (unsigned *)p_mn1,
                                              (float *)p_sumA, nullptr, e0, dh);
  }
  cudaStreamWaitEvent(S, evC, 0);  // n0 + deg0 ready
  {
    int fb = (n0 * (dh / 4) + 255) / 256;
    finalize_rng_kernel<<<fb, 256, 0, S>>>((float *)p_sumA, (float *)p_deg0,
                                           (float *)p_n0, nullptr, kSelf[2][0],
                                           kSelf[2][1], n0, dh);
    dim3 grid((dout + 63) / 64, (n0 + 127) / 128);
    sgemm_bias_128x64<<<grid, 256, 0, S>>>((float *)p_sumA, W2, b2, out, n0,
                                           dout, dh);
  }
}